// round 4
// baseline (speedup 1.0000x reference)
#include <cuda_runtime.h>
#include <cstdint>

// MultiLIF: I[B=32, L=2048, K=512] -> (spikes[B,L,K], spike_series[B,L,K])
// d_out: spikes (B*L*K floats) then spike_series (B*L*K floats).
//
// R3 changes vs R2 (150us):
//  - float2: each thread owns neurons (k, k+1) -> 2 independent chains (ILP=2),
//    LDG.64/STG.64, arithmetic per-lane identical to R2 (rel_err stays 0).
//  - pointer-increment addressing: in-batch store/load addresses are [R+imm],
//    no per-step int64 IMAD chains.
//  - 128 blocks x 64 threads: 2 warps/SM over 128 SMs (memory spread wide,
//    2 SMSPs/SM each running one warp with 2 chains of ILP).

static constexpr int B_ = 32;
static constexpr int L_ = 2048;
static constexpr int K_ = 512;
static constexpr int K2 = K_ / 2;            // float2 elements per timestep row
static constexpr int UNROLL = 16;            // timesteps per prefetch batch
static constexpr int STRIDE2 = UNROLL * K2;  // float2 elems per batch
static constexpr int NTHREADS = B_ * K2;     // 8192

__device__ __forceinline__ float div_const_rn(float x, float b, float y)
{
    // Markstein correctly-rounded x/b (y = RN(1/b)); branch-free, == __fdiv_rn
    // for all normal inputs reachable here.
    float q0 = __fmul_rn(x, y);
    float r  = __fmaf_rn(-b, q0, x);
    return __fmaf_rn(r, y, q0);
}

__device__ __forceinline__ void lif_step1(float It, float& v, float& a,
                                          float& n, float& s_out)
{
    float th = 1.0f + 1.5f * a;
    v = (v - div_const_rn(v, 20.0f, 0.05f)) + It;
    bool fire = (v >= th);
    float s = fire ? 1.0f : 0.0f;
    n = n + s;
    v = fire ? -0.5f : v;
    a = (a - div_const_rn(a, 100.0f, 0.01f)) + s;
    s_out = s;
}

__device__ __forceinline__ void lif_steps2(
    const float2* __restrict__ buf,
    float2* __restrict__ sp, float2* __restrict__ np,
    float2& v, float2& a, float2& n)
{
#pragma unroll
    for (int u = 0; u < UNROLL; u++) {
        float2 It = buf[u];
        float2 s;
        lif_step1(It.x, v.x, a.x, n.x, s.x);
        lif_step1(It.y, v.y, a.y, n.y, s.y);
        __stcs(sp + u * K2, s);
        __stcs(np + u * K2, n);
    }
}

__device__ __forceinline__ void load_batch2(
    const float2* __restrict__ ip, float2* __restrict__ buf)
{
#pragma unroll
    for (int u = 0; u < UNROLL; u++)
        buf[u] = __ldcs(ip + u * K2);
}

__global__ __launch_bounds__(64, 1)
void MultiLIF_kernel(const float2* __restrict__ I,
                     float2* __restrict__ spikes,
                     float2* __restrict__ series)
{
    int gid = blockIdx.x * blockDim.x + threadIdx.x;   // 0..8191
    int b  = gid >> 8;            // /256
    int kp = gid & (K2 - 1);      // float2 column

    int64_t base = (int64_t)b * L_ * K2 + kp;
    const float2* ip = I + base;
    float2* sp = spikes + base;
    float2* np = series + base;

    float2 v = {0.f, 0.f}, a = {0.f, 0.f}, n = {0.f, 0.f};

    float2 buf0[UNROLL], buf1[UNROLL];

    load_batch2(ip, buf0);
    const float2* ipn = ip + STRIDE2;

    constexpr int ITERS = L_ / (2 * UNROLL);   // 64
#pragma unroll 1
    for (int it = 0; it < ITERS; it++) {
        load_batch2(ipn, buf1);
        ipn += STRIDE2;
        lif_steps2(buf0, sp, np, v, a, n);
        sp += STRIDE2; np += STRIDE2;

        // last prefetch would run past the end; re-read a safe address instead
        const float2* pf = (it + 1 < ITERS) ? ipn : ip;
        load_batch2(pf, buf0);
        ipn += STRIDE2;
        lif_steps2(buf1, sp, np, v, a, n);
        sp += STRIDE2; np += STRIDE2;
    }
}

extern "C" void kernel_launch(void* const* d_in, const int* in_sizes, int n_in,
                              void* d_out, int out_size)
{
    const float2* I = (const float2*)d_in[0];
    float2* spikes = (float2*)d_out;
    float2* series = (float2*)((float*)d_out + (int64_t)B_ * L_ * K_);

    dim3 block(64);
    dim3 grid(NTHREADS / 64);    // 128 blocks
    MultiLIF_kernel<<<grid, block>>>(I, spikes, series);
}

// round 5
// speedup vs baseline: 1.0393x; 1.0393x over previous
#include <cuda_runtime.h>
#include <cstdint>

// MultiLIF: I[B=32, L=2048, K=512] -> (spikes[B,L,K], spike_series[B,L,K])
// d_out: spikes (B*L*K floats) then spike_series.
//
// R5 changes vs best (R2, 150us):
//  - speculative reset: next pre-threshold potential computed on BOTH paths
//    (fire path is constant c2 = RN(-0.5 - RN(-0.5/20)) plus I), select AFTER
//    the arithmetic -> FSETP(13cyc) off the critical chain; chain 37 -> ~24cyc.
//    Bit-identical: fire path replays the exact same rounded ops from v=-0.5.
//  - 64 blocks x 256 threads (scalar, 512 warps on 64 SMs = 2 warps/SMSP)
//    so the second warp fills issue slots during the first warp's chain stalls.

static constexpr int B_ = 32;
static constexpr int L_ = 2048;
static constexpr int K_ = 512;
static constexpr int NEURONS = B_ * K_;      // 16384
static constexpr int UNROLL = 16;
static constexpr int STRIDE = UNROLL * K_;

__device__ __forceinline__ float div_const_rn(float x, float b, float y)
{
    // Markstein: correctly-rounded RN(x/b) given y = RN(1/b). Branch-free,
    // == __fdiv_rn for every value reachable here.
    float q0 = __fmul_rn(x, y);
    float r  = __fmaf_rn(-b, q0, x);
    return __fmaf_rn(r, y, q0);
}

// State carried across steps: u = pre-threshold potential AFTER the v-update
// of the current step (i.e. the value compared against th), plus fire flag of
// the current step, plus a, n.
struct LIFState {
    float u;      // v after decay+input, before reset, at current step
    bool  fire;   // u >= th at current step
    float a;
    float n;
};

__device__ __forceinline__ void lif_steps(
    const float* __restrict__ buf,
    float* __restrict__ sp, float* __restrict__ np,
    LIFState& st, float c2)
{
#pragma unroll
    for (int u = 0; u < UNROLL; u++) {
        float It = buf[u];
        // finish previous step's bookkeeping off the critical path
        float s = st.fire ? 1.0f : 0.0f;
        st.n = st.n + s;
        __stcs(sp + u * K_, s);
        __stcs(np + u * K_, st.n);
        // a-update for this step's threshold
        st.a = (st.a - div_const_rn(st.a, 100.0f, 0.01f)) + s;
        float th = 1.0f + 1.5f * st.a;
        // speculative v-update: both reset/no-reset continuations
        float uA = (st.u - div_const_rn(st.u, 20.0f, 0.05f)) + It; // no fire
        float uB = c2 + It;                                        // fired
        float un = st.fire ? uB : uA;
        st.fire = (un >= th);
        st.u = un;
    }
}

__device__ __forceinline__ void load_batch(
    const float* __restrict__ ip, float* __restrict__ buf)
{
#pragma unroll
    for (int u = 0; u < UNROLL; u++)
        buf[u] = __ldcs(ip + u * K_);
}

__global__ __launch_bounds__(256, 1)
void MultiLIF_kernel(const float* __restrict__ I,
                     float* __restrict__ spikes,
                     float* __restrict__ series)
{
    int gid = blockIdx.x * blockDim.x + threadIdx.x;   // 0..16383
    int b = gid >> 9;           // /512
    int k = gid & (K_ - 1);     // %512

    int64_t base = (int64_t)b * L_ * K_ + k;
    const float* ip = I + base;
    float* sp = spikes + base;
    float* np = series + base;

    // fire-path constant: v=-0.5 -> decay with the exact same rounded ops
    float c2 = -0.5f - div_const_rn(-0.5f, 20.0f, 0.05f);

    float buf0[UNROLL], buf1[UNROLL];
    load_batch(ip, buf0);
    const float* ipn = ip + STRIDE;

    // Initial state: v=0, a=0, n=0. Step 0's update from v=0:
    // u0 = (0 - RN(0/20)) + I0 -> handled by starting with u=0, fire=false
    // (fire=false selects uA which replays exactly that arithmetic).
    LIFState st; st.u = 0.0f; st.fire = false; st.a = 0.0f; st.n = 0.0f;
    // NOTE: the loop structure below computes, at the top of each step, the
    // bookkeeping (s, n, reset select) of the PREVIOUS step. For the very
    // first step there is no previous spike: fire=false, s=0, n=0 stored...
    // but that would store step -1. Instead we run a rotated pipeline:
    // compute u/fire for step t inside iteration t, and store results for
    // step t at iteration t+1? That would misalign stores by one batch.
    // Simpler: peel step 0's v/a-update semantics by noting that with
    // u=0, fire=false, a=0, n=0 the "previous bookkeeping" writes s=0,n=0
    // at slot 0 -- WRONG. So we rotate differently: see lif_steps_rot below.
    (void)st;

    // ---- rotated formulation (store current step's s,n after computing) ----
    float uv = 0.0f, a = 0.0f, n = 0.0f;
    bool fire = false;   // "previous step fired" flag; false before step 0

    constexpr int ITERS = L_ / (2 * UNROLL);   // 64
#pragma unroll 1
    for (int it = 0; it < ITERS; it++) {
        load_batch(ipn, buf1);
        ipn += STRIDE;
        {
#pragma unroll
            for (int u = 0; u < UNROLL; u++) {
                float It = buf0[u];
                float th = 1.0f + 1.5f * a;
                float uA = (uv - div_const_rn(uv, 20.0f, 0.05f)) + It;
                float uB = c2 + It;
                float un = fire ? uB : uA;
                bool f = (un >= th);
                float s = f ? 1.0f : 0.0f;
                n = n + s;
                __stcs(sp + u * K_, s);
                __stcs(np + u * K_, n);
                a = (a - div_const_rn(a, 100.0f, 0.01f)) + s;
                uv = un; fire = f;
            }
        }
        sp += STRIDE; np += STRIDE;

        const float* pf = (it + 1 < ITERS) ? ipn : ip;
        load_batch(pf, buf0);
        ipn += STRIDE;
        {
#pragma unroll
            for (int u = 0; u < UNROLL; u++) {
                float It = buf1[u];
                float th = 1.0f + 1.5f * a;
                float uA = (uv - div_const_rn(uv, 20.0f, 0.05f)) + It;
                float uB = c2 + It;
                float un = fire ? uB : uA;
                bool f = (un >= th);
                float s = f ? 1.0f : 0.0f;
                n = n + s;
                __stcs(sp + u * K_, s);
                __stcs(np + u * K_, n);
                a = (a - div_const_rn(a, 100.0f, 0.01f)) + s;
                uv = un; fire = f;
            }
        }
        sp += STRIDE; np += STRIDE;
    }
}

extern "C" void kernel_launch(void* const* d_in, const int* in_sizes, int n_in,
                              void* d_out, int out_size)
{
    const float* I = (const float*)d_in[0];
    float* spikes = (float*)d_out;
    float* series = (float*)d_out + (int64_t)B_ * L_ * K_;

    dim3 block(256);
    dim3 grid(NEURONS / 256);   // 64 blocks -> 8 warps/SM on 64 SMs, 2/SMSP
    MultiLIF_kernel<<<grid, block>>>(I, spikes, series);
}

// round 6
// speedup vs baseline: 1.1203x; 1.0779x over previous
#include <cuda_runtime.h>
#include <cstdint>

// MultiLIF: I[B=32, L=2048, K=512] -> (spikes[B,L,K], spike_series[B,L,K])
// d_out: spikes (B*L*K floats) then spike_series.
//
// R6 change vs R5 (150us): pipeline depth. One-batch prefetch (16 steps ~400cyc
// lead) left DRAM load latency (~600-1000cyc under load) exposed each batch.
// Now: ring of 4 register buffers x 8 timesteps -> loads issued 3 batches
// (24 steps ~600cyc) ahead of use, per warp; x2 warps/SMSP. Arithmetic is
// bit-identical to R5 (speculative-reset + Markstein const division).

static constexpr int B_ = 32;
static constexpr int L_ = 2048;
static constexpr int K_ = 512;
static constexpr int NEURONS = B_ * K_;      // 16384
static constexpr int UNROLL = 8;             // timesteps per batch
static constexpr int NBUF = 4;               // pipeline depth (batches)
static constexpr int NBATCH = L_ / UNROLL;   // 256
static constexpr int STRIDE = UNROLL * K_;   // elements per batch per neuron row

__device__ __forceinline__ float div_const_rn(float x, float b, float y)
{
    // Markstein: correctly-rounded RN(x/b), y = RN(1/b). Branch-free;
    // == __fdiv_rn for all values reachable here.
    float q0 = __fmul_rn(x, y);
    float r  = __fmaf_rn(-b, q0, x);
    return __fmaf_rn(r, y, q0);
}

__global__ __launch_bounds__(256, 1)
void MultiLIF_kernel(const float* __restrict__ I,
                     float* __restrict__ spikes,
                     float* __restrict__ series)
{
    int gid = blockIdx.x * blockDim.x + threadIdx.x;   // 0..16383
    int b = gid >> 9;
    int k = gid & (K_ - 1);

    int64_t base = (int64_t)b * L_ * K_ + k;
    const float* ip = I + base;
    float* sp = spikes + base;
    float* np = series + base;

    // fire-path constant: exact decay of v=-0.5 with the same rounded ops
    const float c2 = -0.5f - div_const_rn(-0.5f, 20.0f, 0.05f);

    float buf[NBUF][UNROLL];

    // prologue: fill batches 0..NBUF-2
#pragma unroll
    for (int p = 0; p < NBUF - 1; p++) {
#pragma unroll
        for (int u = 0; u < UNROLL; u++)
            buf[p][u] = __ldcs(ip + (int64_t)(p * UNROLL + u) * K_);
    }

    float uv = 0.0f, a = 0.0f, n = 0.0f;
    bool fire = false;

    const float* ipn = ip + (int64_t)(NBUF - 1) * STRIDE; // next batch to load
    constexpr int GROUPS = NBATCH / NBUF;                  // 64

#pragma unroll 1
    for (int g = 0; g < GROUPS; g++) {
#pragma unroll
        for (int p = 0; p < NBUF; p++) {
            // prefetch batch (g*NBUF + p + NBUF-1); past the end -> safe addr
            int loadidx = g * NBUF + p + (NBUF - 1);
            const float* lp = (loadidx < NBATCH) ? ipn : ip;
#pragma unroll
            for (int u = 0; u < UNROLL; u++)
                buf[(p + NBUF - 1) & (NBUF - 1)][u] = __ldcs(lp + u * K_);
            ipn += STRIDE;

            // compute batch (g*NBUF + p) from buf[p]
#pragma unroll
            for (int u = 0; u < UNROLL; u++) {
                float It = buf[p][u];
                float th = 1.0f + 1.5f * a;
                float uA = (uv - div_const_rn(uv, 20.0f, 0.05f)) + It;
                float uB = c2 + It;
                float un = fire ? uB : uA;
                bool f = (un >= th);
                float s = f ? 1.0f : 0.0f;
                n = n + s;
                __stcs(sp + u * K_, s);
                __stcs(np + u * K_, n);
                a = (a - div_const_rn(a, 100.0f, 0.01f)) + s;
                uv = un; fire = f;
            }
            sp += STRIDE; np += STRIDE;
        }
    }
}

extern "C" void kernel_launch(void* const* d_in, const int* in_sizes, int n_in,
                              void* d_out, int out_size)
{
    const float* I = (const float*)d_in[0];
    float* spikes = (float*)d_out;
    float* series = (float*)d_out + (int64_t)B_ * L_ * K_;

    dim3 block(256);
    dim3 grid(NEURONS / 256);   // 64 blocks
    MultiLIF_kernel<<<grid, block>>>(I, spikes, series);
}

// round 7
// speedup vs baseline: 1.5021x; 1.3408x over previous
#include <cuda_runtime.h>
#include <cstdint>

// MultiLIF: I[B=32, L=2048, K=512] -> (spikes[B,L,K], spike_series[B,L,K])
// d_out: spikes (B*L*K floats) then spike_series.
//
// R7 change vs R6 (141us): distribution. R6 packed 512 warps on 64 SMs
// (2 warps/SMSP) and was near per-SMSP issue-throughput saturation
// (~84 issue-cyc demand vs ~125 cyc/step observed). Now 128 blocks x 128
// threads -> 512 warps over 128 SMs, 1 warp/SMSP: per-SMSP issue demand
// halves. Single-warp latency exposure is countered by a deeper ring:
// NBUF=8 x UNROLL=8 (56-step load lead ~2300 cyc, ~50 LDGs in flight).
// Arithmetic bit-identical to R5/R6 (speculative reset + Markstein division).

static constexpr int B_ = 32;
static constexpr int L_ = 2048;
static constexpr int K_ = 512;
static constexpr int NEURONS = B_ * K_;      // 16384
static constexpr int UNROLL = 8;             // timesteps per batch
static constexpr int NBUF = 8;               // ring depth (batches)
static constexpr int NBATCH = L_ / UNROLL;   // 256
static constexpr int STRIDE = UNROLL * K_;

__device__ __forceinline__ float div_const_rn(float x, float b, float y)
{
    // Markstein: correctly-rounded RN(x/b), y = RN(1/b). Branch-free;
    // == __fdiv_rn for all values reachable here.
    float q0 = __fmul_rn(x, y);
    float r  = __fmaf_rn(-b, q0, x);
    return __fmaf_rn(r, y, q0);
}

__global__ __launch_bounds__(128, 1)
void MultiLIF_kernel(const float* __restrict__ I,
                     float* __restrict__ spikes,
                     float* __restrict__ series)
{
    int gid = blockIdx.x * blockDim.x + threadIdx.x;   // 0..16383
    int b = gid >> 9;
    int k = gid & (K_ - 1);

    int64_t base = (int64_t)b * L_ * K_ + k;
    const float* ip = I + base;
    float* sp = spikes + base;
    float* np = series + base;

    // fire-path constant: exact decay of v=-0.5 with the same rounded ops
    const float c2 = -0.5f - div_const_rn(-0.5f, 20.0f, 0.05f);

    float buf[NBUF][UNROLL];

    // prologue: fill batches 0..NBUF-2 into slots 0..NBUF-2
#pragma unroll
    for (int p = 0; p < NBUF - 1; p++) {
#pragma unroll
        for (int u = 0; u < UNROLL; u++)
            buf[p][u] = __ldcs(ip + (int64_t)(p * UNROLL + u) * K_);
    }

    float uv = 0.0f, a = 0.0f, n = 0.0f;
    bool fire = false;

    const float* ipn = ip + (int64_t)(NBUF - 1) * STRIDE; // next batch to load
    constexpr int GROUPS = NBATCH / NBUF;                  // 32

#pragma unroll 1
    for (int g = 0; g < GROUPS; g++) {
#pragma unroll
        for (int p = 0; p < NBUF; p++) {
            // prefetch batch (g*NBUF + p + NBUF-1); past the end -> safe addr
            int loadidx = g * NBUF + p + (NBUF - 1);
            const float* lp = (loadidx < NBATCH) ? ipn : ip;
#pragma unroll
            for (int u = 0; u < UNROLL; u++)
                buf[(p + NBUF - 1) & (NBUF - 1)][u] = __ldcs(lp + u * K_);
            ipn += STRIDE;

            // compute batch (g*NBUF + p) from slot p
#pragma unroll
            for (int u = 0; u < UNROLL; u++) {
                float It = buf[p][u];
                float th = 1.0f + 1.5f * a;
                float uA = (uv - div_const_rn(uv, 20.0f, 0.05f)) + It;
                float uB = c2 + It;
                float un = fire ? uB : uA;
                bool f = (un >= th);
                float s = f ? 1.0f : 0.0f;
                n = n + s;
                __stcs(sp + u * K_, s);
                __stcs(np + u * K_, n);
                a = (a - div_const_rn(a, 100.0f, 0.01f)) + s;
                uv = un; fire = f;
            }
            sp += STRIDE; np += STRIDE;
        }
    }
}

extern "C" void kernel_launch(void* const* d_in, const int* in_sizes, int n_in,
                              void* d_out, int out_size)
{
    const float* I = (const float*)d_in[0];
    float* spikes = (float*)d_out;
    float* series = (float*)d_out + (int64_t)B_ * L_ * K_;

    dim3 block(128);
    dim3 grid(NEURONS / 128);   // 128 blocks -> 128 SMs, 1 warp/SMSP
    MultiLIF_kernel<<<grid, block>>>(I, spikes, series);
}